// round 11
// baseline (speedup 1.0000x reference)
#include <cuda_runtime.h>
#include <cuda_fp16.h>
#include <cstdint>

// ============================================================================
// SoftmaxTLinear via stacked-K GEMM on mma.sync (HMMA fp16->fp32), sm_103.
//   out[b,o] = I*N/D + bias[o],  N = sum_i z*e^|z|, D = sum_i e^|z|, z = x*w
//   e^t ~ c0 + c1 t + c2 t^2 + c3 t^3  (deg-3 minimax on [0,0.85])
//   z|z|^k = (x|x|^k)(w|w|^k): separable -> K-stacked fp16 GEMM slices.
//   K_N = 4*1024, K_D = 3*1024.  KC=128, 3-stage cp.async pipeline.
//   R11: 64x32 CTA tiles, 256 threads, 2 CTAs/SM (occupancy 2) so a partner
//   CTA fills the per-chunk barrier/wait bubbles. 8 warps = 2 spatial x
//   4-way K-split, 32x32 warp tiles (inner loop unchanged from R10).
//   D-blocks signal N-blocks via device flag; N-blocks fuse the epilogue.
// ============================================================================

#define B_DIM 256
#define I_DIM 1024
#define O_DIM 1024
#define KN 4096
#define KD 3072
#define KC 128
#define ROWE 136       // smem row stride (128 + 8 pad) in elements
#define A_STG_ELE (64 * ROWE)
#define B_STG_ELE (32 * ROWE)
#define A_STG_BYTES (A_STG_ELE * 2)
#define B_STG_BYTES (B_STG_ELE * 2)
#define DYN_SMEM (3 * (A_STG_BYTES + B_STG_BYTES))   // 78336 B

// minimax coefficients for e^t on [0, 0.85]
#define C0 0.999641f
#define SC1 1.0048289f   // sqrt(1.009681)
#define SC2 0.6690075f   // sqrt(0.447571)
#define SC3 0.5078110f   // sqrt(0.257872)

// ---- scratch (static device memory; no allocations) ----
__device__ __align__(128) __half g_An[B_DIM * KN];
__device__ __align__(128) __half g_Bn[O_DIM * KN];
__device__ __align__(128) __half g_Ad[B_DIM * KD];
__device__ __align__(128) __half g_Bd[O_DIM * KD];
__device__ float g_Dg[B_DIM * O_DIM];
__device__ int   g_flag[128];    // zero-init; N-blocks reset after use

// ---- PTX helpers ----
__device__ __forceinline__ uint32_t smem_u32(const void* p) {
    uint32_t a;
    asm("{ .reg .u64 t; cvta.to.shared.u64 t, %1; cvt.u32.u64 %0, t; }"
        : "=r"(a) : "l"(p));
    return a;
}
#define CP_ASYNC16(dst, src) \
    asm volatile("cp.async.cg.shared.global [%0], [%1], 16;" :: "r"(dst), "l"(src))
#define CP_COMMIT() asm volatile("cp.async.commit_group;" ::: "memory")

#define LDSM_X4(R, addr) \
    asm volatile("ldmatrix.sync.aligned.m8n8.x4.shared.b16 {%0,%1,%2,%3}, [%4];" \
                 : "=r"((R)[0]), "=r"((R)[1]), "=r"((R)[2]), "=r"((R)[3])       \
                 : "r"(addr))

#define MMA_F16(C, A, b0, b1) \
    asm volatile("mma.sync.aligned.m16n8k16.row.col.f32.f16.f16.f32 "          \
                 "{%0,%1,%2,%3}, {%4,%5,%6,%7}, {%8,%9}, {%0,%1,%2,%3};"       \
                 : "+f"((C)[0]), "+f"((C)[1]), "+f"((C)[2]), "+f"((C)[3])      \
                 : "r"((A)[0]), "r"((A)[1]), "r"((A)[2]), "r"((A)[3]),         \
                   "r"(b0), "r"(b1))

// ============================================================================
// prep (merged): blocks 0..255 build A_N/A_D from x; 256..1279 build B_N/B_D
// from w (32x32 transpose tiles). half2 stores throughout.
// ============================================================================
__global__ __launch_bounds__(512) void prep_kernel(const float* __restrict__ x,
                                                   const float* __restrict__ w) {
    const int tid = threadIdx.x;
    if (blockIdx.x < 256) {
        int b = blockIdx.x;
        int i2 = tid * 2;
        float2 v2 = *reinterpret_cast<const float2*>(&x[b * I_DIM + i2]);
        __half s0[2], p1[2], p2[2], p3[2], q1[2], q2[2], q3[2];
        #pragma unroll
        for (int u = 0; u < 2; u++) {
            float v = u ? v2.y : v2.x;
            float av = fabsf(v);
            s0[u] = __float2half(v);
            p1[u] = __float2half(v * av * SC1);
            p2[u] = __float2half(v * v * v * SC2);
            p3[u] = __float2half(v * av * av * av * SC3);
            q1[u] = __float2half(av * SC1);
            q2[u] = __float2half(v * v * SC2);
            q3[u] = __float2half(av * av * av * SC3);
        }
        __half* an = g_An + (long)b * KN + i2;
        *reinterpret_cast<__half2*>(an + 0 * I_DIM) = __halves2half2(s0[0], s0[1]);
        *reinterpret_cast<__half2*>(an + 1 * I_DIM) = __halves2half2(p1[0], p1[1]);
        *reinterpret_cast<__half2*>(an + 2 * I_DIM) = __halves2half2(p2[0], p2[1]);
        *reinterpret_cast<__half2*>(an + 3 * I_DIM) = __halves2half2(p3[0], p3[1]);
        __half* ad = g_Ad + (long)b * KD + i2;
        *reinterpret_cast<__half2*>(ad + 0 * I_DIM) = __halves2half2(q1[0], q1[1]);
        *reinterpret_cast<__half2*>(ad + 1 * I_DIM) = __halves2half2(q2[0], q2[1]);
        *reinterpret_cast<__half2*>(ad + 2 * I_DIM) = __halves2half2(q3[0], q3[1]);
    } else {
        __shared__ float tile[32][33];
        int wb = blockIdx.x - 256;
        int o0 = (wb & 31) * 32;
        int i0 = (wb >> 5) * 32;
        for (int idx = tid; idx < 1024; idx += 512) {
            int r = idx >> 5;
            int c = idx & 31;
            tile[r][c] = w[(long)(i0 + r) * O_DIM + o0 + c];
        }
        __syncthreads();
        int ol  = tid >> 4;
        int il0 = (tid & 15) * 2;
        __half s0[2], p1[2], p2[2], p3[2], q1[2], q2[2], q3[2];
        #pragma unroll
        for (int u = 0; u < 2; u++) {
            float v = tile[il0 + u][ol];
            float av = fabsf(v);
            s0[u] = __float2half(C0 * v);
            p1[u] = __float2half(v * av * SC1);
            p2[u] = __float2half(v * v * v * SC2);
            p3[u] = __float2half(v * av * av * av * SC3);
            q1[u] = __float2half(av * SC1);
            q2[u] = __float2half(v * v * SC2);
            q3[u] = __float2half(av * av * av * SC3);
        }
        __half* bn = g_Bn + (long)(o0 + ol) * KN + i0 + il0;
        *reinterpret_cast<__half2*>(bn + 0 * I_DIM) = __halves2half2(s0[0], s0[1]);
        *reinterpret_cast<__half2*>(bn + 1 * I_DIM) = __halves2half2(p1[0], p1[1]);
        *reinterpret_cast<__half2*>(bn + 2 * I_DIM) = __halves2half2(p2[0], p2[1]);
        *reinterpret_cast<__half2*>(bn + 3 * I_DIM) = __halves2half2(p3[0], p3[1]);
        __half* bd = g_Bd + (long)(o0 + ol) * KD + i0 + il0;
        *reinterpret_cast<__half2*>(bd + 0 * I_DIM) = __halves2half2(q1[0], q1[1]);
        *reinterpret_cast<__half2*>(bd + 1 * I_DIM) = __halves2half2(q2[0], q2[1]);
        *reinterpret_cast<__half2*>(bd + 2 * I_DIM) = __halves2half2(q3[0], q3[1]);
    }
}

// ============================================================================
// Fused GEMM: blocks 0..127 = N-GEMM (K=4096) + epilogue; 128..255 = D-GEMM
// (K=3072) -> g_Dg + flag. 64x32 CTA tile, 256 threads = 8 warps arranged
// as 2 spatial (32-row halves) x 4-way K-split; 32x32 warp tiles. KC=128,
// 3-stage cp.async pipeline, 2 CTAs/SM. End: 3-slice smem reduction.
// ============================================================================
__global__ __launch_bounds__(256, 2) void gemm_kernel(const float* __restrict__ bias,
                                                      float* __restrict__ out) {
    extern __shared__ __half smem[];
    __half* sA = smem;                         // [3][A_STG_ELE]
    __half* sB = smem + 3 * A_STG_ELE;         // [3][B_STG_ELE]

    const int bid = blockIdx.x;
    const bool isN = bid < 128;
    const int t = isN ? bid : bid - 128;
    const int mTile = t & 3;                   // 4 m-tiles of 64
    const int nTile = t >> 2;                  // 32 n-tiles of 32
    const __half* A  = isN ? g_An : g_Ad;
    const __half* Bm = isN ? g_Bn : g_Bd;
    const int K = isN ? KN : KD;
    const int nChunks = K / KC;                // 32 or 24

    const int tid = threadIdx.x;
    const int wid = tid >> 5;
    const int l   = tid & 31;
    const int kw  = wid & 3;                   // K-slice 0..3 (2 k16 each)
    const int mw  = wid >> 2;                  // 0..1 -> m offset mw*32

    const __half* gA0 = A  + (long)(mTile * 64) * K;
    const __half* gB0 = Bm + (long)(nTile * 32) * K;

    // cp.async A: 64 rows x 16 granules = 1024; 4/thread.
    const int aRow = tid >> 2;
    const int aG   = tid & 3;
    const long gOffA = (long)aRow * K + aG * 8;
    const uint32_t sOffA = (uint32_t)(aRow * ROWE + aG * 8) * 2;
    // cp.async B: 32 rows x 16 granules = 512; 2/thread.
    const int bRow = tid >> 3;
    const int bG   = tid & 7;
    const long gOffB = (long)bRow * K + bG * 8;
    const uint32_t sOffB = (uint32_t)(bRow * ROWE + bG * 8) * 2;

    const uint32_t sAu = smem_u32(sA);
    const uint32_t sBu = smem_u32(sB);

    auto load_chunk = [&](int j, int s) {
        const __half* gA = gA0 + gOffA + j * KC;
        uint32_t dA = sAu + s * A_STG_BYTES + sOffA;
        #pragma unroll
        for (int u = 0; u < 4; u++)
            CP_ASYNC16(dA + u * 64, gA + u * 32);
        const __half* gB = gB0 + gOffB + j * KC;
        uint32_t dB = sBu + s * B_STG_BYTES + sOffB;
        CP_ASYNC16(dB,       gB);
        CP_ASYNC16(dB + 128, gB + 64);
        CP_COMMIT();
    };

    // ldmatrix x4 offsets (stage-relative bytes), per 16-row sub-tile
    const int r_ = l & 7, q = l >> 3;
    uint32_t aOff[2], bOff[2];
    #pragma unroll
    for (int u = 0; u < 2; u++) {
        aOff[u] = (uint32_t)((mw * 32 + u * 16 + (q & 1) * 8 + r_) * ROWE +
                             (q >> 1) * 8) * 2;
        bOff[u] = (uint32_t)((u * 16 + (q >> 1) * 8 + r_) * ROWE +
                             (q & 1) * 8) * 2;
    }
    const uint32_t kByte = (uint32_t)kw * 64;   // this warp's k16 pair

    float acc[2][2][2][4];   // [ma][nb][g][c]
    #pragma unroll
    for (int ma = 0; ma < 2; ma++)
        #pragma unroll
        for (int nb = 0; nb < 2; nb++)
            #pragma unroll
            for (int g = 0; g < 2; g++)
                #pragma unroll
                for (int c = 0; c < 4; c++) acc[ma][nb][g][c] = 0.0f;

    load_chunk(0, 0);
    load_chunk(1, 1);

    int s = 0;
    for (int j = 0; j < nChunks; j++) {
        asm volatile("cp.async.wait_group 1;" ::: "memory");
        __syncthreads();
        if (j + 2 < nChunks) {
            int s2 = s + 2; if (s2 >= 3) s2 -= 3;
            load_chunk(j + 2, s2);
        } else {
            CP_COMMIT();   // keep group accounting uniform through the tail
        }

        const uint32_t baseA = sAu + s * A_STG_BYTES + kByte;
        const uint32_t baseB = sBu + s * B_STG_BYTES + kByte;
        #pragma unroll
        for (int sub = 0; sub < 2; sub++) {
            uint32_t af[2][4], bf[2][4];
            LDSM_X4(af[0], baseA + aOff[0] + sub * 32);
            LDSM_X4(af[1], baseA + aOff[1] + sub * 32);
            LDSM_X4(bf[0], baseB + bOff[0] + sub * 32);
            LDSM_X4(bf[1], baseB + bOff[1] + sub * 32);
            #pragma unroll
            for (int ma = 0; ma < 2; ma++)
                #pragma unroll
                for (int nb = 0; nb < 2; nb++) {
                    MMA_F16(acc[ma][nb][0], af[ma], bf[nb][0], bf[nb][1]);
                    MMA_F16(acc[ma][nb][1], af[ma], bf[nb][2], bf[nb][3]);
                }
        }
        if (++s >= 3) s -= 3;
    }

    // ---- cross-warp K-slice reduction (reuse pipeline smem) ----
    __syncthreads();
    float* rb = reinterpret_cast<float*>(smem);   // 3 x 64x32 f32 = 24KB
    const int row_l = l >> 2;
    const int col_l = (l & 3) * 2;

    if (kw > 0) {
        float* dst = rb + (kw - 1) * 2048;
        #pragma unroll
        for (int ma = 0; ma < 2; ma++)
            #pragma unroll
            for (int nb = 0; nb < 2; nb++)
                #pragma unroll
                for (int g = 0; g < 2; g++) {
                    int rr = mw * 32 + ma * 16 + row_l;
                    int cc = nb * 16 + g * 8 + col_l;
                    *reinterpret_cast<float2*>(&dst[rr * 32 + cc]) =
                        make_float2(acc[ma][nb][g][0], acc[ma][nb][g][1]);
                    *reinterpret_cast<float2*>(&dst[(rr + 8) * 32 + cc]) =
                        make_float2(acc[ma][nb][g][2], acc[ma][nb][g][3]);
                }
    }
    __syncthreads();

    if (kw == 0) {
        #pragma unroll
        for (int ma = 0; ma < 2; ma++)
            #pragma unroll
            for (int nb = 0; nb < 2; nb++)
                #pragma unroll
                for (int g = 0; g < 2; g++) {
                    int rr = mw * 32 + ma * 16 + row_l;
                    int cc = nb * 16 + g * 8 + col_l;
                    #pragma unroll
                    for (int sl = 0; sl < 3; sl++) {
                        float2 v0 = *reinterpret_cast<float2*>(
                            &rb[sl * 2048 + rr * 32 + cc]);
                        float2 v1 = *reinterpret_cast<float2*>(
                            &rb[sl * 2048 + (rr + 8) * 32 + cc]);
                        acc[ma][nb][g][0] += v0.x;
                        acc[ma][nb][g][1] += v0.y;
                        acc[ma][nb][g][2] += v1.x;
                        acc[ma][nb][g][3] += v1.y;
                    }
                }
    }

    if (!isN) {
        if (kw == 0) {
            #pragma unroll
            for (int ma = 0; ma < 2; ma++)
                #pragma unroll
                for (int nb = 0; nb < 2; nb++)
                    #pragma unroll
                    for (int g = 0; g < 2; g++) {
                        int rr = mTile * 64 + mw * 32 + ma * 16 + row_l;
                        int cc = nTile * 32 + nb * 16 + g * 8 + col_l;
                        *reinterpret_cast<float2*>(&g_Dg[rr * O_DIM + cc]) =
                            make_float2(acc[ma][nb][g][0], acc[ma][nb][g][1]);
                        *reinterpret_cast<float2*>(&g_Dg[(rr + 8) * O_DIM + cc]) =
                            make_float2(acc[ma][nb][g][2], acc[ma][nb][g][3]);
                    }
        }
        __syncthreads();
        __threadfence();                       // release
        if (tid == 0) atomicExch(&g_flag[t], 1);
    } else {
        if (tid == 0) {
            while (atomicAdd(&g_flag[t], 0) == 0) { }
        }
        __syncthreads();
        __threadfence();                       // acquire
        if (kw == 0) {
            const float D0 = C0 * 1024.0f;
            #pragma unroll
            for (int ma = 0; ma < 2; ma++)
                #pragma unroll
                for (int nb = 0; nb < 2; nb++)
                    #pragma unroll
                    for (int g = 0; g < 2; g++) {
                        int rr = mTile * 64 + mw * 32 + ma * 16 + row_l;
                        int cc = nTile * 32 + nb * 16 + g * 8 + col_l;
                        float2 d0 = *reinterpret_cast<const float2*>(
                            &g_Dg[rr * O_DIM + cc]);
                        float2 d1 = *reinterpret_cast<const float2*>(
                            &g_Dg[(rr + 8) * O_DIM + cc]);
                        float2 bb = *reinterpret_cast<const float2*>(&bias[cc]);
                        float2 r0, r1;
                        r0.x = 1024.0f * acc[ma][nb][g][0] / (D0 + d0.x) + bb.x;
                        r0.y = 1024.0f * acc[ma][nb][g][1] / (D0 + d0.y) + bb.y;
                        r1.x = 1024.0f * acc[ma][nb][g][2] / (D0 + d1.x) + bb.x;
                        r1.y = 1024.0f * acc[ma][nb][g][3] / (D0 + d1.y) + bb.y;
                        *reinterpret_cast<float2*>(&out[rr * O_DIM + cc]) = r0;
                        *reinterpret_cast<float2*>(&out[(rr + 8) * O_DIM + cc]) = r1;
                    }
        }
        __syncthreads();
        if (tid == 0) atomicExch(&g_flag[t], 0);   // reset for next replay
    }
}

// ============================================================================
extern "C" void kernel_launch(void* const* d_in, const int* in_sizes, int n_in,
                              void* d_out, int out_size) {
    const float* x    = (const float*)d_in[0];
    const float* w    = (const float*)d_in[1];
    const float* bias = (const float*)d_in[2];
    float* out        = (float*)d_out;

    cudaFuncSetAttribute(gemm_kernel, cudaFuncAttributeMaxDynamicSharedMemorySize,
                         DYN_SMEM);

    prep_kernel<<<1280, 512>>>(x, w);
    gemm_kernel<<<256, 256, DYN_SMEM>>>(bias, out);
}

// round 14
// speedup vs baseline: 1.0504x; 1.0504x over previous
#include <cuda_runtime.h>
#include <cuda_fp16.h>
#include <cstdint>

// ============================================================================
// SoftmaxTLinear via stacked-K GEMM on mma.sync (HMMA fp16->fp32), sm_103.
//   out[b,o] = I*N/D + bias[o],  N = sum_i z*e^|z|, D = sum_i e^|z|, z = x*w
//   e^t ~ c0 + c1 t + c2 t^2 + c3 t^3  (deg-3 minimax on [0,0.85])
//   z|z|^k = (x|x|^k)(w|w|^k): separable -> K-stacked fp16 GEMM slices.
//   K_N = 4096, K_D = 3072.  KC=128, 3-stage cp.async pipeline.
//   64x64 tiles + CTA-level K-split: each tile = 2 CTAs of 256 threads over
//   half K -> grid 256, 2 CTAs/SM, half the chunks on the critical path and
//   partner-CTA latency hiding. Flag chain ordered producer-before-consumer:
//     bids   0..63  Ns1: N half-K partial -> g_Npart, nf
//     bids  64..127 Ds1: D half-K partial -> g_Dpart, dpf
//     bids 128..191 Ds0: D half-K + partial -> g_Dg, df
//     bids 192..255 Ns0: N half-K + partial, wait df -> epilogue -> out
//   R14 fix: cp.async granule stride was u*64 elems (OOB reads + uncovered
//   columns); correct is u*32 elems / u*64 bytes for 4 threads/row.
// ============================================================================

#define B_DIM 256
#define I_DIM 1024
#define O_DIM 1024
#define KN 4096
#define KD 3072
#define KC 128
#define ROWE 136       // smem row stride (128 + 8 pad) in elements
#define STG_ELE (64 * ROWE)
#define STG_BYTES (STG_ELE * 2)            // 17408 B per 64-row tile
#define DYN_SMEM (6 * STG_BYTES)           // 3 stages x (A + B) = 104448 B

// minimax coefficients for e^t on [0, 0.85]
#define C0 0.999641f
#define SC1 1.0048289f   // sqrt(1.009681)
#define SC2 0.6690075f   // sqrt(0.447571)
#define SC3 0.5078110f   // sqrt(0.257872)

// ---- scratch (static device memory; no allocations) ----
__device__ __align__(128) __half g_An[B_DIM * KN];
__device__ __align__(128) __half g_Bn[O_DIM * KN];
__device__ __align__(128) __half g_Ad[B_DIM * KD];
__device__ __align__(128) __half g_Bd[O_DIM * KD];
__device__ float g_Npart[64 * 4096];   // per-tile N half-K partial
__device__ float g_Dpart[64 * 4096];   // per-tile D half-K partial
__device__ float g_Dg[B_DIM * O_DIM];  // full D
__device__ int   g_nf[64];             // zero-init; consumers reset after use
__device__ int   g_dpf[64];
__device__ int   g_df[64];

// ---- PTX helpers ----
__device__ __forceinline__ uint32_t smem_u32(const void* p) {
    uint32_t a;
    asm("{ .reg .u64 t; cvta.to.shared.u64 t, %1; cvt.u32.u64 %0, t; }"
        : "=r"(a) : "l"(p));
    return a;
}
#define CP_ASYNC16(dst, src) \
    asm volatile("cp.async.cg.shared.global [%0], [%1], 16;" :: "r"(dst), "l"(src))
#define CP_COMMIT() asm volatile("cp.async.commit_group;" ::: "memory")

#define LDSM_X4(R, addr) \
    asm volatile("ldmatrix.sync.aligned.m8n8.x4.shared.b16 {%0,%1,%2,%3}, [%4];" \
                 : "=r"((R)[0]), "=r"((R)[1]), "=r"((R)[2]), "=r"((R)[3])       \
                 : "r"(addr))

#define MMA_F16(C, A, b0, b1) \
    asm volatile("mma.sync.aligned.m16n8k16.row.col.f32.f16.f16.f32 "          \
                 "{%0,%1,%2,%3}, {%4,%5,%6,%7}, {%8,%9}, {%0,%1,%2,%3};"       \
                 : "+f"((C)[0]), "+f"((C)[1]), "+f"((C)[2]), "+f"((C)[3])      \
                 : "r"((A)[0]), "r"((A)[1]), "r"((A)[2]), "r"((A)[3]),         \
                   "r"(b0), "r"(b1))

// ============================================================================
// prep (merged): blocks 0..255 build A_N/A_D from x; 256..1279 build B_N/B_D
// from w (32x32 transpose tiles). half2 stores throughout.
// ============================================================================
__global__ __launch_bounds__(512) void prep_kernel(const float* __restrict__ x,
                                                   const float* __restrict__ w) {
    const int tid = threadIdx.x;
    if (blockIdx.x < 256) {
        int b = blockIdx.x;
        int i2 = tid * 2;
        float2 v2 = *reinterpret_cast<const float2*>(&x[b * I_DIM + i2]);
        __half s0[2], p1[2], p2[2], p3[2], q1[2], q2[2], q3[2];
        #pragma unroll
        for (int u = 0; u < 2; u++) {
            float v = u ? v2.y : v2.x;
            float av = fabsf(v);
            s0[u] = __float2half(v);
            p1[u] = __float2half(v * av * SC1);
            p2[u] = __float2half(v * v * v * SC2);
            p3[u] = __float2half(v * av * av * av * SC3);
            q1[u] = __float2half(av * SC1);
            q2[u] = __float2half(v * v * SC2);
            q3[u] = __float2half(av * av * av * SC3);
        }
        __half* an = g_An + (long)b * KN + i2;
        *reinterpret_cast<__half2*>(an + 0 * I_DIM) = __halves2half2(s0[0], s0[1]);
        *reinterpret_cast<__half2*>(an + 1 * I_DIM) = __halves2half2(p1[0], p1[1]);
        *reinterpret_cast<__half2*>(an + 2 * I_DIM) = __halves2half2(p2[0], p2[1]);
        *reinterpret_cast<__half2*>(an + 3 * I_DIM) = __halves2half2(p3[0], p3[1]);
        __half* ad = g_Ad + (long)b * KD + i2;
        *reinterpret_cast<__half2*>(ad + 0 * I_DIM) = __halves2half2(q1[0], q1[1]);
        *reinterpret_cast<__half2*>(ad + 1 * I_DIM) = __halves2half2(q2[0], q2[1]);
        *reinterpret_cast<__half2*>(ad + 2 * I_DIM) = __halves2half2(q3[0], q3[1]);
    } else {
        __shared__ float tile[32][33];
        int wb = blockIdx.x - 256;
        int o0 = (wb & 31) * 32;
        int i0 = (wb >> 5) * 32;
        for (int idx = tid; idx < 1024; idx += 512) {
            int r = idx >> 5;
            int c = idx & 31;
            tile[r][c] = w[(long)(i0 + r) * O_DIM + o0 + c];
        }
        __syncthreads();
        int ol  = tid >> 4;
        int il0 = (tid & 15) * 2;
        __half s0[2], p1[2], p2[2], p3[2], q1[2], q2[2], q3[2];
        #pragma unroll
        for (int u = 0; u < 2; u++) {
            float v = tile[il0 + u][ol];
            float av = fabsf(v);
            s0[u] = __float2half(C0 * v);
            p1[u] = __float2half(v * av * SC1);
            p2[u] = __float2half(v * v * v * SC2);
            p3[u] = __float2half(v * av * av * av * SC3);
            q1[u] = __float2half(av * SC1);
            q2[u] = __float2half(v * v * SC2);
            q3[u] = __float2half(av * av * av * SC3);
        }
        __half* bn = g_Bn + (long)(o0 + ol) * KN + i0 + il0;
        *reinterpret_cast<__half2*>(bn + 0 * I_DIM) = __halves2half2(s0[0], s0[1]);
        *reinterpret_cast<__half2*>(bn + 1 * I_DIM) = __halves2half2(p1[0], p1[1]);
        *reinterpret_cast<__half2*>(bn + 2 * I_DIM) = __halves2half2(p2[0], p2[1]);
        *reinterpret_cast<__half2*>(bn + 3 * I_DIM) = __halves2half2(p3[0], p3[1]);
        __half* bd = g_Bd + (long)(o0 + ol) * KD + i0 + il0;
        *reinterpret_cast<__half2*>(bd + 0 * I_DIM) = __halves2half2(q1[0], q1[1]);
        *reinterpret_cast<__half2*>(bd + 1 * I_DIM) = __halves2half2(q2[0], q2[1]);
        *reinterpret_cast<__half2*>(bd + 2 * I_DIM) = __halves2half2(q3[0], q3[1]);
    }
}

// ============================================================================
// K-split fused GEMM. 64x64 tile per CTA-pair, 256 thr = 8 warps =
// 2x2 spatial (32x32 warp tiles) x 2 K-sub-slices. KC=128, 3 stages.
// ============================================================================
__global__ __launch_bounds__(256, 2) void gemm_kernel(const float* __restrict__ bias,
                                                      float* __restrict__ out) {
    extern __shared__ __half smem[];
    __half* sA = smem;                 // [3][STG_ELE]
    __half* sB = smem + 3 * STG_ELE;

    const int bid = blockIdx.x;
    const int role = bid >> 6;         // 0=Ns1 1=Ds1 2=Ds0 3=Ns0
    const int t = bid & 63;
    const bool isN = (role == 0) || (role == 3);
    const int kslice = (role <= 1) ? 1 : 0;
    const int mTile = t & 3;
    const int nTile = t >> 2;
    const __half* A  = isN ? g_An : g_Ad;
    const __half* Bm = isN ? g_Bn : g_Bd;
    const int K = isN ? KN : KD;
    const int halfK = K >> 1;
    const int nChunks = halfK / KC;    // 16 (N) or 12 (D)

    const int tid = threadIdx.x;
    const int wid = tid >> 5;
    const int l   = tid & 31;
    const int kw  = wid & 1;           // K-sub-slice within chunk (4 k16 each)
    const int sw  = wid >> 1;          // spatial 0..3
    const int mw  = sw >> 1;
    const int nw  = sw & 1;

    const __half* gA0 = A  + (long)(mTile * 64) * K + (long)kslice * halfK;
    const __half* gB0 = Bm + (long)(nTile * 64) * K + (long)kslice * halfK;

    // cp.async: 64 rows x 16 granules; 4 threads/row, 4 granules/thread.
    // Thread covers elements cG*8 + u*32 (u=0..3) -> {0,8,16,24}+{0,32,64,96}.
    const int cRow = tid >> 2;
    const int cG   = tid & 3;
    const long gOff = (long)cRow * K + cG * 8;
    const uint32_t sOff = (uint32_t)(cRow * ROWE + cG * 8) * 2;
    const uint32_t sAu = smem_u32(sA);
    const uint32_t sBu = smem_u32(sB);

    auto load_chunk = [&](int j, int s) {
        const __half* gA = gA0 + gOff + j * KC;
        const __half* gB = gB0 + gOff + j * KC;
        uint32_t dA = sAu + s * STG_BYTES + sOff;
        uint32_t dB = sBu + s * STG_BYTES + sOff;
        #pragma unroll
        for (int u = 0; u < 4; u++) {
            CP_ASYNC16(dA + u * 64, gA + u * 32);
            CP_ASYNC16(dB + u * 64, gB + u * 32);
        }
        CP_COMMIT();
    };

    // ldmatrix x4 offsets (stage-relative bytes), per 16-row sub-tile
    const int r_ = l & 7, q = l >> 3;
    uint32_t aOff[2], bOff[2];
    #pragma unroll
    for (int u = 0; u < 2; u++) {
        aOff[u] = (uint32_t)((mw * 32 + u * 16 + (q & 1) * 8 + r_) * ROWE +
                             (q >> 1) * 8) * 2;
        bOff[u] = (uint32_t)((nw * 32 + u * 16 + (q >> 1) * 8 + r_) * ROWE +
                             (q & 1) * 8) * 2;
    }
    const uint32_t kByte = (uint32_t)kw * 128;   // this warp's 4-k16 slab

    float acc[2][2][2][4];   // [ma][nb][g][c]
    #pragma unroll
    for (int ma = 0; ma < 2; ma++)
        #pragma unroll
        for (int nb = 0; nb < 2; nb++)
            #pragma unroll
            for (int g = 0; g < 2; g++)
                #pragma unroll
                for (int c = 0; c < 4; c++) acc[ma][nb][g][c] = 0.0f;

    load_chunk(0, 0);
    load_chunk(1, 1);

    int s = 0;
    for (int j = 0; j < nChunks; j++) {
        asm volatile("cp.async.wait_group 1;" ::: "memory");
        __syncthreads();
        if (j + 2 < nChunks) {
            int s2 = s + 2; if (s2 >= 3) s2 -= 3;
            load_chunk(j + 2, s2);
        } else {
            CP_COMMIT();   // keep group accounting uniform through the tail
        }

        const uint32_t baseA = sAu + s * STG_BYTES + kByte;
        const uint32_t baseB = sBu + s * STG_BYTES + kByte;
        #pragma unroll
        for (int ks = 0; ks < 4; ks++) {
            uint32_t af[2][4], bf[2][4];
            LDSM_X4(af[0], baseA + aOff[0] + ks * 32);
            LDSM_X4(af[1], baseA + aOff[1] + ks * 32);
            LDSM_X4(bf[0], baseB + bOff[0] + ks * 32);
            LDSM_X4(bf[1], baseB + bOff[1] + ks * 32);
            #pragma unroll
            for (int ma = 0; ma < 2; ma++)
                #pragma unroll
                for (int nb = 0; nb < 2; nb++) {
                    MMA_F16(acc[ma][nb][0], af[ma], bf[nb][0], bf[nb][1]);
                    MMA_F16(acc[ma][nb][1], af[ma], bf[nb][2], bf[nb][3]);
                }
        }
        if (++s >= 3) s -= 3;
    }

    // ---- intra-CTA 2-slice reduction (reuse pipeline smem) ----
    __syncthreads();
    float* rb = reinterpret_cast<float*>(smem);   // 64x64 f32 = 16KB
    const int row_l = l >> 2;
    const int col_l = (l & 3) * 2;

    if (kw == 1) {
        #pragma unroll
        for (int ma = 0; ma < 2; ma++)
            #pragma unroll
            for (int nb = 0; nb < 2; nb++)
                #pragma unroll
                for (int g = 0; g < 2; g++) {
                    int rr = mw * 32 + ma * 16 + row_l;
                    int cc = nw * 32 + nb * 16 + g * 8 + col_l;
                    *reinterpret_cast<float2*>(&rb[rr * 64 + cc]) =
                        make_float2(acc[ma][nb][g][0], acc[ma][nb][g][1]);
                    *reinterpret_cast<float2*>(&rb[(rr + 8) * 64 + cc]) =
                        make_float2(acc[ma][nb][g][2], acc[ma][nb][g][3]);
                }
    }
    __syncthreads();

    if (kw == 0) {
        #pragma unroll
        for (int ma = 0; ma < 2; ma++)
            #pragma unroll
            for (int nb = 0; nb < 2; nb++)
                #pragma unroll
                for (int g = 0; g < 2; g++) {
                    int rr = mw * 32 + ma * 16 + row_l;
                    int cc = nw * 32 + nb * 16 + g * 8 + col_l;
                    float2 v0 = *reinterpret_cast<float2*>(&rb[rr * 64 + cc]);
                    float2 v1 = *reinterpret_cast<float2*>(&rb[(rr + 8) * 64 + cc]);
                    acc[ma][nb][g][0] += v0.x;
                    acc[ma][nb][g][1] += v0.y;
                    acc[ma][nb][g][2] += v1.x;
                    acc[ma][nb][g][3] += v1.y;
                }
    }

    // kw==0 warps now hold this CTA's half-K 64x64 result.
    if (role == 0 || role == 1) {
        // producers: write partial tile, release flag
        float* part = (role == 0 ? g_Npart : g_Dpart) + (long)t * 4096;
        if (kw == 0) {
            #pragma unroll
            for (int ma = 0; ma < 2; ma++)
                #pragma unroll
                for (int nb = 0; nb < 2; nb++)
                    #pragma unroll
                    for (int g = 0; g < 2; g++) {
                        int rr = mw * 32 + ma * 16 + row_l;
                        int cc = nw * 32 + nb * 16 + g * 8 + col_l;
                        *reinterpret_cast<float2*>(&part[rr * 64 + cc]) =
                            make_float2(acc[ma][nb][g][0], acc[ma][nb][g][1]);
                        *reinterpret_cast<float2*>(&part[(rr + 8) * 64 + cc]) =
                            make_float2(acc[ma][nb][g][2], acc[ma][nb][g][3]);
                    }
        }
        __syncthreads();
        __threadfence();
        if (tid == 0) atomicExch(role == 0 ? &g_nf[t] : &g_dpf[t], 1);
    } else if (role == 2) {
        // D combiner: acc += g_Dpart -> g_Dg (global coords), release df
        if (tid == 0) {
            while (atomicAdd(&g_dpf[t], 0) == 0) { __nanosleep(64); }
        }
        __syncthreads();
        __threadfence();
        const float* part = g_Dpart + (long)t * 4096;
        if (kw == 0) {
            #pragma unroll
            for (int ma = 0; ma < 2; ma++)
                #pragma unroll
                for (int nb = 0; nb < 2; nb++)
                    #pragma unroll
                    for (int g = 0; g < 2; g++) {
                        int rl = mw * 32 + ma * 16 + row_l;
                        int cl = nw * 32 + nb * 16 + g * 8 + col_l;
                        float2 p0 = *reinterpret_cast<const float2*>(&part[rl * 64 + cl]);
                        float2 p1 = *reinterpret_cast<const float2*>(&part[(rl + 8) * 64 + cl]);
                        int rr = mTile * 64 + rl;
                        int cc = nTile * 64 + cl;
                        *reinterpret_cast<float2*>(&g_Dg[rr * O_DIM + cc]) =
                            make_float2(acc[ma][nb][g][0] + p0.x,
                                        acc[ma][nb][g][1] + p0.y);
                        *reinterpret_cast<float2*>(&g_Dg[(rr + 8) * O_DIM + cc]) =
                            make_float2(acc[ma][nb][g][2] + p1.x,
                                        acc[ma][nb][g][3] + p1.y);
                    }
        }
        __syncthreads();
        if (tid == 0) {
            atomicExch(&g_dpf[t], 0);          // reset for next replay
            __threadfence();
            atomicExch(&g_df[t], 1);
        }
    } else {
        // N combiner + epilogue
        if (tid == 0) {
            while (atomicAdd(&g_nf[t], 0) == 0) { __nanosleep(64); }
            while (atomicAdd(&g_df[t], 0) == 0) { __nanosleep(64); }
        }
        __syncthreads();
        __threadfence();
        const float* part = g_Npart + (long)t * 4096;
        if (kw == 0) {
            const float D0 = C0 * 1024.0f;
            #pragma unroll
            for (int ma = 0; ma < 2; ma++)
                #pragma unroll
                for (int nb = 0; nb < 2; nb++)
                    #pragma unroll
                    for (int g = 0; g < 2; g++) {
                        int rl = mw * 32 + ma * 16 + row_l;
                        int cl = nw * 32 + nb * 16 + g * 8 + col_l;
                        float2 p0 = *reinterpret_cast<const float2*>(&part[rl * 64 + cl]);
                        float2 p1 = *reinterpret_cast<const float2*>(&part[(rl + 8) * 64 + cl]);
                        int rr = mTile * 64 + rl;
                        int cc = nTile * 64 + cl;
                        float2 d0 = *reinterpret_cast<const float2*>(&g_Dg[rr * O_DIM + cc]);
                        float2 d1 = *reinterpret_cast<const float2*>(&g_Dg[(rr + 8) * O_DIM + cc]);
                        float2 bb = *reinterpret_cast<const float2*>(&bias[cc]);
                        float2 r0, r1;
                        r0.x = 1024.0f * (acc[ma][nb][g][0] + p0.x) / (D0 + d0.x) + bb.x;
                        r0.y = 1024.0f * (acc[ma][nb][g][1] + p0.y) / (D0 + d0.y) + bb.y;
                        r1.x = 1024.0f * (acc[ma][nb][g][2] + p1.x) / (D0 + d1.x) + bb.x;
                        r1.y = 1024.0f * (acc[ma][nb][g][3] + p1.y) / (D0 + d1.y) + bb.y;
                        *reinterpret_cast<float2*>(&out[rr * O_DIM + cc]) = r0;
                        *reinterpret_cast<float2*>(&out[(rr + 8) * O_DIM + cc]) = r1;
                    }
        }
        __syncthreads();
        if (tid == 0) {
            atomicExch(&g_nf[t], 0);           // reset for next replay
            atomicExch(&g_df[t], 0);
        }
    }
}

// ============================================================================
extern "C" void kernel_launch(void* const* d_in, const int* in_sizes, int n_in,
                              void* d_out, int out_size) {
    const float* x    = (const float*)d_in[0];
    const float* w    = (const float*)d_in[1];
    const float* bias = (const float*)d_in[2];
    float* out        = (float*)d_out;

    cudaFuncSetAttribute(gemm_kernel, cudaFuncAttributeMaxDynamicSharedMemorySize,
                         DYN_SMEM);

    prep_kernel<<<1280, 512>>>(x, w);
    gemm_kernel<<<256, 256, DYN_SMEM>>>(bias, out);
}